// round 15
// baseline (speedup 1.0000x reference)
#include <cuda_runtime.h>
#include <cuda_fp16.h>
#include <mma.h>

using namespace nvcuda;

#define EMB   2048
#define NSTEP 2048
#define NB    2
#define G4    (4*EMB)

#define CTAS  128
#define EPC   16          // e-values per CTA
#define NROWS 64          // 4 gates * EPC
#define NTHR  512         // 16 warps (4/SMSP)
#define RPW   4           // rows per warp (consecutive, same gate)
#define FPAD  32          // flag padding (ints) -> 128B per flag line

// All weights fp16. Per row (2048 cols):
//   cols [0,512)     fp16 in registers (uint2 = 4 cols; m in [0,4))
//   cols [512,2048)  fp16 in smem      (m in [4,16))
// h is fp16 in smem (8KB), staged once per step (1 uint4 per thread).

#define SH_W_U (NROWS*768)          // 49152 uints (fp16x2) = 192KB
#define SH_H_U (NB*EMB/2)           // 2048 uints (half2)   = 8KB
#define SH_G_F (NROWS*2)
#define SMEM_BYTES (SH_W_U*4 + SH_H_U*4 + SH_G_F*4)

__device__ __align__(16) __half g_Whalf[(size_t)G4*EMB];        // fp16 Wih+Whh
__device__ float  g_bcomb[G4];
__device__ __align__(16) __half g_hseq16[(size_t)NSTEP*NB*EMB]; // [t][b][e] fp16
__device__ __align__(16) __half g_Wout16[(size_t)EMB*EMB];      // fp16 Wout
__device__ int    g_flag[CTAS*FPAD];                            // padded step flags

__device__ __forceinline__ float sigmoid_fast(float v) {
    return __fdividef(1.0f, 1.0f + __expf(-v));
}
__device__ __forceinline__ float tanh_fast(float v) {
    return __fdividef(2.0f, 1.0f + __expf(-2.0f * v)) - 1.0f;
}

// ---------------------------------------------------------------------------
__global__ void prep_kernel(const float* __restrict__ Wih, const float* __restrict__ Whh,
                            const float* __restrict__ bih, const float* __restrict__ bhh,
                            const float* __restrict__ Wout) {
    size_t n = (size_t)G4 * EMB;
    size_t stride = (size_t)gridDim.x * blockDim.x;
    for (size_t i = (size_t)blockIdx.x * blockDim.x + threadIdx.x; i < n; i += stride)
        g_Whalf[i] = __float2half(Wih[i] + Whh[i]);
    size_t nw = (size_t)EMB * EMB;
    for (size_t i = (size_t)blockIdx.x * blockDim.x + threadIdx.x; i < nw; i += stride)
        g_Wout16[i] = __float2half(Wout[i]);
    int i = blockIdx.x * blockDim.x + threadIdx.x;
    if (i < G4) g_bcomb[i] = bih[i] + bhh[i];
    if (i < CTAS) g_flag[i * FPAD] = 0;
}

// ---------------------------------------------------------------------------
// persistent LSTM: 128 CTAs x 512 threads (16 warps, 4/SMSP), occupancy 1.
// Warp w owns rows w*4..w*4+3 (same gate g = w>>2) over the full K.
// Inner math: HFMA2 with chunked f32 flushes.
// Grid barrier: distributed padded flags (R2-proven release/acquire shape).
// ---------------------------------------------------------------------------
__global__ void __launch_bounds__(NTHR, 1)
lstm_kernel(const float* __restrict__ x, const float* __restrict__ Wih) {
    extern __shared__ float sh[];
    unsigned* sh_w = (unsigned*)sh;              // [64][768] fp16x2, cols [512,2048)
    unsigned* sh_h16 = (unsigned*)(sh + SH_W_U); // [2][1024] half2 words
    float* sh_g = sh + SH_W_U + SH_H_U;          // [64][2] activated gates

    const int tid  = threadIdx.x;
    const int lane = tid & 31;
    const int wid  = tid >> 5;
    const int e0   = blockIdx.x * EPC;
    const int gate = wid >> 2;

    int rl[RPW], Rg[RPW];
    float bias[RPW];
#pragma unroll
    for (int r = 0; r < RPW; r++) {
        rl[r] = wid * RPW + r;
        Rg[r] = (rl[r] >> 4) * EMB + e0 + (rl[r] & 15);
        bias[r] = g_bcomb[Rg[r]];
    }

    // fill smem fp16 weights: cols [512,2048) for the CTA's 64 rows
    {
        const int n4 = NROWS * 192;              // uint4 count (8 halves each)
        for (int i = tid; i < n4; i += NTHR) {
            int rr = i / 192, q4 = i % 192;
            int grow = (rr >> 4) * EMB + e0 + (rr & 15);
            uint4 v = *(const uint4*)&g_Whalf[(size_t)grow * EMB + 512 + q4 * 8];
            ((uint4*)sh_w)[rr * 192 + q4] = v;
        }
    }

    // register fp16 weights: cols [0,512), uint2 = 4 cols, c = 4*(lane+32m), m<4
    uint2 wregA[RPW][4];
#pragma unroll
    for (int r = 0; r < RPW; r++)
#pragma unroll
        for (int m = 0; m < 4; m++)
            wregA[r][m] = *(const uint2*)&g_Whalf[(size_t)Rg[r] * EMB + 4 * (lane + 32 * m)];

    float c_reg = 0.0f;
    const int my_el = tid >> 1, my_b = tid & 1;

    for (int t = 0; t < NSTEP; t++) {
        float acc[RPW][2];

        if (t == 0) {
            // gates0 = x @ W_ih^T in f32 (one-time), operands direct from global
#pragma unroll
            for (int r = 0; r < RPW; r++) { acc[r][0] = 0.0f; acc[r][1] = 0.0f; }
#pragma unroll 4
            for (int j = 0; j < 64; j++) {
                int k = lane + 32 * j;
                float h0 = __ldg(&x[k]), h1 = __ldg(&x[EMB + k]);
#pragma unroll
                for (int r = 0; r < RPW; r++) {
                    float w = __ldg(&Wih[(size_t)Rg[r] * EMB + k]);
                    acc[r][0] += w * h0; acc[r][1] += w * h1;
                }
            }
            __syncthreads();   // uniform with t>0 step shape
        } else {
            // distributed grid barrier: wait for all CTAs to finish step t-1
            if (tid < CTAS) {
                while (((volatile int*)g_flag)[tid * FPAD] < t) { }
            }
            __threadfence();               // acquire
            __syncthreads();

            // stage h_{t-1} (fp16, 8KB): 512 threads x uint4
            ((uint4*)sh_h16)[tid] =
                __ldcg(((const uint4*)(g_hseq16 + (size_t)(t - 1) * NB * EMB)) + tid);
            __syncthreads();

            __half2 accH[RPW][2];
            float2  accF[RPW][2];
#pragma unroll
            for (int r = 0; r < RPW; r++) {
                accH[r][0] = __half2half2(__ushort_as_half(0));
                accH[r][1] = __half2half2(__ushort_as_half(0));
                accF[r][0] = make_float2(0.f, 0.f);
                accF[r][1] = make_float2(0.f, 0.f);
            }

            const uint2* sw2 = (const uint2*)sh_w;
#pragma unroll
            for (int m = 0; m < 16; m++) {
                int p = 2 * (lane + 32 * m);     // half2-word index (4 cols)
                uint2 ha = *(const uint2*)&sh_h16[p];
                uint2 hb = *(const uint2*)&sh_h16[1024 + p];
                __half2 hA0 = *(__half2*)&ha.x, hA1 = *(__half2*)&ha.y;
                __half2 hB0 = *(__half2*)&hb.x, hB1 = *(__half2*)&hb.y;
#pragma unroll
                for (int r = 0; r < RPW; r++) {
                    uint2 wv = (m < 4) ? wregA[r][m]
                                       : sw2[rl[r] * 384 + (lane + 32 * m - 128)];
                    __half2 w0 = *(__half2*)&wv.x, w1 = *(__half2*)&wv.y;
                    accH[r][0] = __hfma2(w0, hA0, accH[r][0]);
                    accH[r][0] = __hfma2(w1, hA1, accH[r][0]);
                    accH[r][1] = __hfma2(w0, hB0, accH[r][1]);
                    accH[r][1] = __hfma2(w1, hB1, accH[r][1]);
                }
                // flush fp16 partials to f32 every 4 m-iters (16 terms)
                if ((m & 3) == 3) {
#pragma unroll
                    for (int r = 0; r < RPW; r++)
#pragma unroll
                        for (int b = 0; b < 2; b++) {
                            float2 f = __half22float2(accH[r][b]);
                            accF[r][b].x += f.x; accF[r][b].y += f.y;
                            accH[r][b] = __half2half2(__ushort_as_half(0));
                        }
                }
            }
#pragma unroll
            for (int r = 0; r < RPW; r++) {
                acc[r][0] = accF[r][0].x + accF[r][0].y;
                acc[r][1] = accF[r][1].x + accF[r][1].y;
            }
        }

        // butterfly reduce: all lanes end with complete sums
#pragma unroll
        for (int r = 0; r < RPW; r++)
#pragma unroll
            for (int b = 0; b < 2; b++) {
                float v = acc[r][b];
                v += __shfl_xor_sync(0xffffffffu, v, 16);
                v += __shfl_xor_sync(0xffffffffu, v, 8);
                v += __shfl_xor_sync(0xffffffffu, v, 4);
                v += __shfl_xor_sync(0xffffffffu, v, 2);
                v += __shfl_xor_sync(0xffffffffu, v, 1);
                acc[r][b] = v;
            }

        // lanes 0..7: apply this warp's (single-gate) activation, publish
        if (lane < 8) {
            int r = lane >> 1, b = lane & 1;
            float v = acc[r][b] + bias[r];
            v = (gate == 2) ? tanh_fast(v) : sigmoid_fast(v);
            sh_g[rl[r] * 2 + b] = v;
        }
        __syncthreads();

        // warp 0 (owners): combine gates, update c, store h (fp16, full seq)
        if (tid < 32) {
            float ai = sh_g[(0  + my_el) * 2 + my_b];
            float af = sh_g[(16 + my_el) * 2 + my_b];
            float ag = sh_g[(32 + my_el) * 2 + my_b];
            float ao = sh_g[(48 + my_el) * 2 + my_b];
            float cn = af * c_reg + ai * ag;
            c_reg = cn;
            float h = ao * tanh_fast(cn);
            g_hseq16[((size_t)t * NB + my_b) * EMB + e0 + my_el] = __float2half(h);
        }
        __threadfence();               // release (all threads; R2-proven shape)
        __syncthreads();

        // announce completion of step t (skip after final step)
        if (t != NSTEP - 1 && tid == 0)
            ((volatile int*)g_flag)[blockIdx.x * FPAD] = t + 1;
    }
}

// ---------------------------------------------------------------------------
// output projection via wmma fp16 tensor cores:
// out[b][t][n] = hseq[t][b][:] . W_out[n][:] + b_out[n]
// A = g_hseq16 [M=4096][K=2048] row-major (m = t*2+b)
// B = g_Wout16 [N=2048][K=2048] -> matrix_b col_major with ld = EMB
// CTA tile 128x128, 8 warps (2 m x 4 n), warp tile 64x32 = 4x2 frags.
// ---------------------------------------------------------------------------
#define GLDA 40   // smem leading dim (halves), 80B row stride (16B-aligned)

__global__ void __launch_bounds__(256)
out_gemm_wmma(const float* __restrict__ bout, float* __restrict__ out) {
    __shared__ __half As[128 * GLDA];
    __shared__ __half Bs[128 * GLDA];
    __shared__ float  Cst[8 * 16 * 20];

    const int tid = threadIdx.x;
    const int lane = tid & 31;
    const int wid  = tid >> 5;
    const int warp_m = wid & 1;       // 2 x 64 rows
    const int warp_n = wid >> 1;      // 4 x 32 cols
    const int m0 = blockIdx.y * 128;
    const int n0 = blockIdx.x * 128;

    wmma::fragment<wmma::accumulator, 16, 16, 16, float> fc[4][2];
#pragma unroll
    for (int fi = 0; fi < 4; fi++)
#pragma unroll
        for (int fj = 0; fj < 2; fj++)
            wmma::fill_fragment(fc[fi][fj], 0.0f);

    for (int k0 = 0; k0 < EMB; k0 += 32) {
        // cooperative load of A(128x32) and B(128x32) tiles, uint4 = 8 halves
#pragma unroll
        for (int u = 0; u < 2; u++) {
            int i = tid + u * 256;            // [0,512)
            int row = i >> 2, cg = (i & 3) * 8;
            *(uint4*)&As[row * GLDA + cg] =
                *(const uint4*)&g_hseq16[(size_t)(m0 + row) * EMB + k0 + cg];
            *(uint4*)&Bs[row * GLDA + cg] =
                *(const uint4*)&g_Wout16[(size_t)(n0 + row) * EMB + k0 + cg];
        }
        __syncthreads();

#pragma unroll
        for (int ks = 0; ks < 2; ks++) {
            wmma::fragment<wmma::matrix_a, 16, 16, 16, __half, wmma::row_major> fa[4];
            wmma::fragment<wmma::matrix_b, 16, 16, 16, __half, wmma::col_major> fb[2];
#pragma unroll
            for (int fi = 0; fi < 4; fi++)
                wmma::load_matrix_sync(fa[fi],
                    &As[(warp_m * 64 + fi * 16) * GLDA + ks * 16], GLDA);
#pragma unroll
            for (int fj = 0; fj < 2; fj++)
                wmma::load_matrix_sync(fb[fj],
                    &Bs[(warp_n * 32 + fj * 16) * GLDA + ks * 16], GLDA);
#pragma unroll
            for (int fi = 0; fi < 4; fi++)
#pragma unroll
                for (int fj = 0; fj < 2; fj++)
                    wmma::mma_sync(fc[fi][fj], fa[fi], fb[fj], fc[fi][fj]);
        }
        __syncthreads();
    }

    // epilogue: frag -> smem staging -> scattered rows of out (+bias)
    float* bufw = &Cst[wid * 320];
    const int r = lane & 15, h8 = lane >> 4;
#pragma unroll
    for (int fi = 0; fi < 4; fi++) {
#pragma unroll
        for (int fj = 0; fj < 2; fj++) {
            wmma::store_matrix_sync(bufw, fc[fi][fj], 20, wmma::mem_row_major);
            __syncwarp();
            int m = m0 + warp_m * 64 + fi * 16 + r;
            int nb = n0 + warp_n * 32 + fj * 16 + h8 * 8;
            float* orow = &out[((size_t)(m & 1) * NSTEP + (m >> 1)) * EMB];
#pragma unroll
            for (int u = 0; u < 8; u++)
                orow[nb + u] = bufw[r * 20 + h8 * 8 + u] + bout[nb + u];
            __syncwarp();
        }
    }
}

// ---------------------------------------------------------------------------
extern "C" void kernel_launch(void* const* d_in, const int* in_sizes, int n_in,
                              void* d_out, int out_size) {
    const float* x    = (const float*)d_in[0];
    const float* Wih  = (const float*)d_in[1];
    const float* Whh  = (const float*)d_in[2];
    const float* bih  = (const float*)d_in[3];
    const float* bhh  = (const float*)d_in[4];
    const float* Wout = (const float*)d_in[5];
    const float* bout = (const float*)d_in[6];
    float* out = (float*)d_out;

    cudaFuncSetAttribute(lstm_kernel, cudaFuncAttributeMaxDynamicSharedMemorySize, SMEM_BYTES);

    prep_kernel<<<4096, 256>>>(Wih, Whh, bih, bhh, Wout);
    lstm_kernel<<<CTAS, NTHR, SMEM_BYTES>>>(x, Wih);
    dim3 ggrid(EMB / 128, (NSTEP * NB) / 128);
    out_gemm_wmma<<<ggrid, 256>>>(bout, out);
}

// round 16
// speedup vs baseline: 1.0024x; 1.0024x over previous
#include <cuda_runtime.h>
#include <cuda_fp16.h>
#include <mma.h>

using namespace nvcuda;

#define EMB   2048
#define NSTEP 2048
#define NB    2
#define G4    (4*EMB)

#define CTAS  128
#define EPC   16          // e-values per CTA
#define NROWS 64          // 4 gates * EPC
#define NTHR  512         // 16 warps (4/SMSP)
#define RPW   4           // rows per warp (consecutive, same gate)
#define FPAD  32          // flag padding (ints) -> 128B per flag line

// All weights fp16. Per row (2048 cols):
//   cols [0,512)     fp16 in registers (uint2 = 4 cols; m in [0,4))
//   cols [512,2048)  fp16 in smem      (m in [4,16))
// h is fp16 in smem (8KB), staged once per step (1 uint4 per thread).

#define SH_W_U (NROWS*768)          // 49152 uints (fp16x2) = 192KB
#define SH_H_U (NB*EMB/2)           // 2048 uints (half2)   = 8KB
#define SH_G_F (NROWS*2)
#define SMEM_BYTES (SH_W_U*4 + SH_H_U*4 + SH_G_F*4)

__device__ __align__(16) __half g_Whalf[(size_t)G4*EMB];        // fp16 Wih+Whh
__device__ float  g_bcomb[G4];
__device__ __align__(16) __half g_hseq16[(size_t)NSTEP*NB*EMB]; // [t][b][e] fp16
__device__ __align__(16) __half g_Wout16[(size_t)EMB*EMB];      // fp16 Wout
__device__ int    g_flag[CTAS*FPAD];                            // padded step flags

__device__ __forceinline__ float sigmoid_fast(float v) {
    return __fdividef(1.0f, 1.0f + __expf(-v));
}
__device__ __forceinline__ float tanh_fast(float v) {
    return __fdividef(2.0f, 1.0f + __expf(-2.0f * v)) - 1.0f;
}

// ---------------------------------------------------------------------------
__global__ void prep_kernel(const float* __restrict__ Wih, const float* __restrict__ Whh,
                            const float* __restrict__ bih, const float* __restrict__ bhh,
                            const float* __restrict__ Wout) {
    size_t n = (size_t)G4 * EMB;
    size_t stride = (size_t)gridDim.x * blockDim.x;
    for (size_t i = (size_t)blockIdx.x * blockDim.x + threadIdx.x; i < n; i += stride)
        g_Whalf[i] = __float2half(Wih[i] + Whh[i]);
    size_t nw = (size_t)EMB * EMB;
    for (size_t i = (size_t)blockIdx.x * blockDim.x + threadIdx.x; i < nw; i += stride)
        g_Wout16[i] = __float2half(Wout[i]);
    int i = blockIdx.x * blockDim.x + threadIdx.x;
    if (i < G4) g_bcomb[i] = bih[i] + bhh[i];
    if (i < CTAS) g_flag[i * FPAD] = 0;
}

// ---------------------------------------------------------------------------
// persistent LSTM: 128 CTAs x 512 threads (16 warps, 4/SMSP), occupancy 1.
// Warp w owns rows w*4..w*4+3 (same gate g = w>>2) over the full K.
// Inner math: HFMA2 with chunked f32 flushes.
// Grid barrier: distributed padded flags (R2-proven release/acquire shape).
// ---------------------------------------------------------------------------
__global__ void __launch_bounds__(NTHR, 1)
lstm_kernel(const float* __restrict__ x, const float* __restrict__ Wih) {
    extern __shared__ float sh[];
    unsigned* sh_w = (unsigned*)sh;              // [64][768] fp16x2, cols [512,2048)
    unsigned* sh_h16 = (unsigned*)(sh + SH_W_U); // [2][1024] half2 words
    float* sh_g = sh + SH_W_U + SH_H_U;          // [64][2] activated gates

    const int tid  = threadIdx.x;
    const int lane = tid & 31;
    const int wid  = tid >> 5;
    const int e0   = blockIdx.x * EPC;
    const int gate = wid >> 2;

    int rl[RPW], Rg[RPW];
    float bias[RPW];
#pragma unroll
    for (int r = 0; r < RPW; r++) {
        rl[r] = wid * RPW + r;
        Rg[r] = (rl[r] >> 4) * EMB + e0 + (rl[r] & 15);
        bias[r] = g_bcomb[Rg[r]];
    }

    // fill smem fp16 weights: cols [512,2048) for the CTA's 64 rows
    {
        const int n4 = NROWS * 192;              // uint4 count (8 halves each)
        for (int i = tid; i < n4; i += NTHR) {
            int rr = i / 192, q4 = i % 192;
            int grow = (rr >> 4) * EMB + e0 + (rr & 15);
            uint4 v = *(const uint4*)&g_Whalf[(size_t)grow * EMB + 512 + q4 * 8];
            ((uint4*)sh_w)[rr * 192 + q4] = v;
        }
    }

    // register fp16 weights: cols [0,512), uint2 = 4 cols, c = 4*(lane+32m), m<4
    uint2 wregA[RPW][4];
#pragma unroll
    for (int r = 0; r < RPW; r++)
#pragma unroll
        for (int m = 0; m < 4; m++)
            wregA[r][m] = *(const uint2*)&g_Whalf[(size_t)Rg[r] * EMB + 4 * (lane + 32 * m)];

    float c_reg = 0.0f;
    const int my_el = tid >> 1, my_b = tid & 1;

    for (int t = 0; t < NSTEP; t++) {
        float acc[RPW][2];

        if (t == 0) {
            // gates0 = x @ W_ih^T in f32 (one-time), operands direct from global
#pragma unroll
            for (int r = 0; r < RPW; r++) { acc[r][0] = 0.0f; acc[r][1] = 0.0f; }
#pragma unroll 4
            for (int j = 0; j < 64; j++) {
                int k = lane + 32 * j;
                float h0 = __ldg(&x[k]), h1 = __ldg(&x[EMB + k]);
#pragma unroll
                for (int r = 0; r < RPW; r++) {
                    float w = __ldg(&Wih[(size_t)Rg[r] * EMB + k]);
                    acc[r][0] += w * h0; acc[r][1] += w * h1;
                }
            }
            __syncthreads();   // uniform with t>0 step shape
        } else {
            // distributed grid barrier: wait for all CTAs to finish step t-1
            if (tid < CTAS) {
                while (((volatile int*)g_flag)[tid * FPAD] < t) { }
            }
            __threadfence();               // acquire
            __syncthreads();

            // stage h_{t-1} (fp16, 8KB): 512 threads x uint4
            ((uint4*)sh_h16)[tid] =
                __ldcg(((const uint4*)(g_hseq16 + (size_t)(t - 1) * NB * EMB)) + tid);
            __syncthreads();

            __half2 accH[RPW][2];
            float2  accF[RPW][2];
#pragma unroll
            for (int r = 0; r < RPW; r++) {
                accH[r][0] = __half2half2(__ushort_as_half(0));
                accH[r][1] = __half2half2(__ushort_as_half(0));
                accF[r][0] = make_float2(0.f, 0.f);
                accF[r][1] = make_float2(0.f, 0.f);
            }

            const uint2* sw2 = (const uint2*)sh_w;
#pragma unroll
            for (int m = 0; m < 16; m++) {
                int p = 2 * (lane + 32 * m);     // half2-word index (4 cols)
                uint2 ha = *(const uint2*)&sh_h16[p];
                uint2 hb = *(const uint2*)&sh_h16[1024 + p];
                __half2 hA0 = *(__half2*)&ha.x, hA1 = *(__half2*)&ha.y;
                __half2 hB0 = *(__half2*)&hb.x, hB1 = *(__half2*)&hb.y;
#pragma unroll
                for (int r = 0; r < RPW; r++) {
                    uint2 wv = (m < 4) ? wregA[r][m]
                                       : sw2[rl[r] * 384 + (lane + 32 * m - 128)];
                    __half2 w0 = *(__half2*)&wv.x, w1 = *(__half2*)&wv.y;
                    accH[r][0] = __hfma2(w0, hA0, accH[r][0]);
                    accH[r][0] = __hfma2(w1, hA1, accH[r][0]);
                    accH[r][1] = __hfma2(w0, hB0, accH[r][1]);
                    accH[r][1] = __hfma2(w1, hB1, accH[r][1]);
                }
                // flush fp16 partials to f32 every 4 m-iters (16 terms)
                if ((m & 3) == 3) {
#pragma unroll
                    for (int r = 0; r < RPW; r++)
#pragma unroll
                        for (int b = 0; b < 2; b++) {
                            float2 f = __half22float2(accH[r][b]);
                            accF[r][b].x += f.x; accF[r][b].y += f.y;
                            accH[r][b] = __half2half2(__ushort_as_half(0));
                        }
                }
            }
#pragma unroll
            for (int r = 0; r < RPW; r++) {
                acc[r][0] = accF[r][0].x + accF[r][0].y;
                acc[r][1] = accF[r][1].x + accF[r][1].y;
            }
        }

        // butterfly reduce: all lanes end with complete sums
#pragma unroll
        for (int r = 0; r < RPW; r++)
#pragma unroll
            for (int b = 0; b < 2; b++) {
                float v = acc[r][b];
                v += __shfl_xor_sync(0xffffffffu, v, 16);
                v += __shfl_xor_sync(0xffffffffu, v, 8);
                v += __shfl_xor_sync(0xffffffffu, v, 4);
                v += __shfl_xor_sync(0xffffffffu, v, 2);
                v += __shfl_xor_sync(0xffffffffu, v, 1);
                acc[r][b] = v;
            }

        // lanes 0..7: apply this warp's (single-gate) activation, publish
        if (lane < 8) {
            int r = lane >> 1, b = lane & 1;
            float v = acc[r][b] + bias[r];
            v = (gate == 2) ? tanh_fast(v) : sigmoid_fast(v);
            sh_g[rl[r] * 2 + b] = v;
        }
        __syncthreads();

        // warp 0 (owners): combine gates, update c, store h (fp16, full seq)
        if (tid < 32) {
            float ai = sh_g[(0  + my_el) * 2 + my_b];
            float af = sh_g[(16 + my_el) * 2 + my_b];
            float ag = sh_g[(32 + my_el) * 2 + my_b];
            float ao = sh_g[(48 + my_el) * 2 + my_b];
            float cn = af * c_reg + ai * ag;
            c_reg = cn;
            float h = ao * tanh_fast(cn);
            g_hseq16[((size_t)t * NB + my_b) * EMB + e0 + my_el] = __float2half(h);
        }
        __threadfence();               // release (all threads; R2-proven shape)
        __syncthreads();

        // announce completion of step t (skip after final step)
        if (t != NSTEP - 1 && tid == 0)
            ((volatile int*)g_flag)[blockIdx.x * FPAD] = t + 1;
    }
}

// ---------------------------------------------------------------------------
// output projection via wmma fp16 tensor cores:
// out[b][t][n] = hseq[t][b][:] . W_out[n][:] + b_out[n]
// A = g_hseq16 [M=4096][K=2048] row-major (m = t*2+b)
// B = g_Wout16 [N=2048][K=2048] -> matrix_b col_major with ld = EMB
// CTA tile 128x128, 8 warps (2 m x 4 n), warp tile 64x32 = 4x2 frags.
// ---------------------------------------------------------------------------
#define GLDA 40   // smem leading dim (halves), 80B row stride (16B-aligned)

__global__ void __launch_bounds__(256)
out_gemm_wmma(const float* __restrict__ bout, float* __restrict__ out) {
    __shared__ __half As[128 * GLDA];
    __shared__ __half Bs[128 * GLDA];
    __shared__ float  Cst[8 * 16 * 20];

    const int tid = threadIdx.x;
    const int lane = tid & 31;
    const int wid  = tid >> 5;
    const int warp_m = wid & 1;       // 2 x 64 rows
    const int warp_n = wid >> 1;      // 4 x 32 cols
    const int m0 = blockIdx.y * 128;
    const int n0 = blockIdx.x * 128;

    wmma::fragment<wmma::accumulator, 16, 16, 16, float> fc[4][2];
#pragma unroll
    for (int fi = 0; fi < 4; fi++)
#pragma unroll
        for (int fj = 0; fj < 2; fj++)
            wmma::fill_fragment(fc[fi][fj], 0.0f);

    for (int k0 = 0; k0 < EMB; k0 += 32) {
        // cooperative load of A(128x32) and B(128x32) tiles, uint4 = 8 halves
#pragma unroll
        for (int u = 0; u < 2; u++) {
            int i = tid + u * 256;            // [0,512)
            int row = i >> 2, cg = (i & 3) * 8;
            *(uint4*)&As[row * GLDA + cg] =
                *(const uint4*)&g_hseq16[(size_t)(m0 + row) * EMB + k0 + cg];
            *(uint4*)&Bs[row * GLDA + cg] =
                *(const uint4*)&g_Wout16[(size_t)(n0 + row) * EMB + k0 + cg];
        }
        __syncthreads();

#pragma unroll
        for (int ks = 0; ks < 2; ks++) {
            wmma::fragment<wmma::matrix_a, 16, 16, 16, __half, wmma::row_major> fa[4];
            wmma::fragment<wmma::matrix_b, 16, 16, 16, __half, wmma::col_major> fb[2];
#pragma unroll
            for (int fi = 0; fi < 4; fi++)
                wmma::load_matrix_sync(fa[fi],
                    &As[(warp_m * 64 + fi * 16) * GLDA + ks * 16], GLDA);
#pragma unroll
            for (int fj = 0; fj < 2; fj++)
                wmma::load_matrix_sync(fb[fj],
                    &Bs[(warp_n * 32 + fj * 16) * GLDA + ks * 16], GLDA);
#pragma unroll
            for (int fi = 0; fi < 4; fi++)
#pragma unroll
                for (int fj = 0; fj < 2; fj++)
                    wmma::mma_sync(fc[fi][fj], fa[fi], fb[fj], fc[fi][fj]);
        }
        __syncthreads();
    }

    // epilogue: frag -> smem staging -> scattered rows of out (+bias)
    float* bufw = &Cst[wid * 320];
    const int r = lane & 15, h8 = lane >> 4;
#pragma unroll
    for (int fi = 0; fi < 4; fi++) {
#pragma unroll
        for (int fj = 0; fj < 2; fj++) {
            wmma::store_matrix_sync(bufw, fc[fi][fj], 20, wmma::mem_row_major);
            __syncwarp();
            int m = m0 + warp_m * 64 + fi * 16 + r;
            int nb = n0 + warp_n * 32 + fj * 16 + h8 * 8;
            float* orow = &out[((size_t)(m & 1) * NSTEP + (m >> 1)) * EMB];
#pragma unroll
            for (int u = 0; u < 8; u++)
                orow[nb + u] = bufw[r * 20 + h8 * 8 + u] + bout[nb + u];
            __syncwarp();
        }
    }
}

// ---------------------------------------------------------------------------
extern "C" void kernel_launch(void* const* d_in, const int* in_sizes, int n_in,
                              void* d_out, int out_size) {
    const float* x    = (const float*)d_in[0];
    const float* Wih  = (const float*)d_in[1];
    const float* Whh  = (const float*)d_in[2];
    const float* bih  = (const float*)d_in[3];
    const float* bhh  = (const float*)d_in[4];
    const float* Wout = (const float*)d_in[5];
    const float* bout = (const float*)d_in[6];
    float* out = (float*)d_out;

    cudaFuncSetAttribute(lstm_kernel, cudaFuncAttributeMaxDynamicSharedMemorySize, SMEM_BYTES);

    prep_kernel<<<4096, 256>>>(Wih, Whh, bih, bhh, Wout);
    lstm_kernel<<<CTAS, NTHR, SMEM_BYTES>>>(x, Wih);
    dim3 ggrid(EMB / 128, (NSTEP * NB) / 128);
    out_gemm_wmma<<<ggrid, 256>>>(bout, out);
}

// round 17
// speedup vs baseline: 1.0960x; 1.0934x over previous
#include <cuda_runtime.h>
#include <cuda_fp16.h>
#include <mma.h>

using namespace nvcuda;

#define EMB   2048
#define NSTEP 2048
#define NB    2
#define G4    (4*EMB)

#define CTAS  128
#define EPC   16          // e-values per CTA
#define NROWS 64          // 4 gates * EPC
#define NTHR  512         // 16 warps (4/SMSP)
#define RPW   4           // rows per warp (consecutive, same gate)

// All weights fp16. Per row (2048 cols):
//   cols [0,512)     fp16 in registers (uint2 = 4 cols; m in [0,4))
//   cols [512,2048)  fp16 in smem      (m in [4,16))
// h is fp16 in smem (8KB), staged once per step (1 uint4 per thread).

#define SH_W_U (NROWS*768)          // 49152 uints (fp16x2) = 192KB
#define SH_H_U (NB*EMB/2)           // 2048 uints (half2)   = 8KB
#define SH_G_F (NROWS*2)
#define SMEM_BYTES (SH_W_U*4 + SH_H_U*4 + SH_G_F*4)

__device__ __align__(16) __half g_Whalf[(size_t)G4*EMB];        // fp16 Wih+Whh
__device__ float  g_bcomb[G4];
__device__ __align__(16) __half g_hseq16[(size_t)NSTEP*NB*EMB]; // [t][b][e] fp16
__device__ __align__(16) __half g_Wout16[(size_t)EMB*EMB];      // fp16 Wout
__device__ unsigned g_bar;

__device__ __forceinline__ float sigmoid_fast(float v) {
    return __fdividef(1.0f, 1.0f + __expf(-v));
}
__device__ __forceinline__ float tanh_fast(float v) {
    return __fdividef(2.0f, 1.0f + __expf(-2.0f * v)) - 1.0f;
}

// ---------------------------------------------------------------------------
__global__ void prep_kernel(const float* __restrict__ Wih, const float* __restrict__ Whh,
                            const float* __restrict__ bih, const float* __restrict__ bhh,
                            const float* __restrict__ Wout) {
    size_t n = (size_t)G4 * EMB;
    size_t stride = (size_t)gridDim.x * blockDim.x;
    for (size_t i = (size_t)blockIdx.x * blockDim.x + threadIdx.x; i < n; i += stride)
        g_Whalf[i] = __float2half(Wih[i] + Whh[i]);
    size_t nw = (size_t)EMB * EMB;
    for (size_t i = (size_t)blockIdx.x * blockDim.x + threadIdx.x; i < nw; i += stride)
        g_Wout16[i] = __float2half(Wout[i]);
    int i = blockIdx.x * blockDim.x + threadIdx.x;
    if (i < G4) g_bcomb[i] = bih[i] + bhh[i];
    if (i == 0) g_bar = 0u;
}

// ---------------------------------------------------------------------------
// persistent LSTM: 128 CTAs x 512 threads (16 warps, 4/SMSP), occupancy 1.
// Warp w owns rows w*4..w*4+3 (same gate g = w>>2) over the full K.
// Inner math: HFMA2 with chunked f32 flushes.
// Sync skeleton: 3 syncs/step. Release = warp-0 fence + tid0 atomicAdd in the
// tail (no trailing block sync); acquire = tid0 volatile poll + fence + sync
// at the top of the next step.
// ---------------------------------------------------------------------------
__global__ void __launch_bounds__(NTHR, 1)
lstm_kernel(const float* __restrict__ x, const float* __restrict__ Wih) {
    extern __shared__ float sh[];
    unsigned* sh_w = (unsigned*)sh;              // [64][768] fp16x2, cols [512,2048)
    unsigned* sh_h16 = (unsigned*)(sh + SH_W_U); // [2][1024] half2 words
    float* sh_g = sh + SH_W_U + SH_H_U;          // [64][2] activated gates

    const int tid  = threadIdx.x;
    const int lane = tid & 31;
    const int wid  = tid >> 5;
    const int e0   = blockIdx.x * EPC;
    const int gate = wid >> 2;

    int rl[RPW], Rg[RPW];
    float bias[RPW];
#pragma unroll
    for (int r = 0; r < RPW; r++) {
        rl[r] = wid * RPW + r;
        Rg[r] = (rl[r] >> 4) * EMB + e0 + (rl[r] & 15);
        bias[r] = g_bcomb[Rg[r]];
    }

    // fill smem fp16 weights: cols [512,2048) for the CTA's 64 rows
    {
        const int n4 = NROWS * 192;              // uint4 count (8 halves each)
        for (int i = tid; i < n4; i += NTHR) {
            int rr = i / 192, q4 = i % 192;
            int grow = (rr >> 4) * EMB + e0 + (rr & 15);
            uint4 v = *(const uint4*)&g_Whalf[(size_t)grow * EMB + 512 + q4 * 8];
            ((uint4*)sh_w)[rr * 192 + q4] = v;
        }
    }

    // register fp16 weights: cols [0,512), uint2 = 4 cols, c = 4*(lane+32m), m<4
    uint2 wregA[RPW][4];
#pragma unroll
    for (int r = 0; r < RPW; r++)
#pragma unroll
        for (int m = 0; m < 4; m++)
            wregA[r][m] = *(const uint2*)&g_Whalf[(size_t)Rg[r] * EMB + 4 * (lane + 32 * m)];

    float c_reg = 0.0f;
    const int my_el = tid >> 1, my_b = tid & 1;

    for (int t = 0; t < NSTEP; t++) {
        float acc[RPW][2];

        if (t == 0) {
            // gates0 = x @ W_ih^T in f32 (one-time), operands direct from global
#pragma unroll
            for (int r = 0; r < RPW; r++) { acc[r][0] = 0.0f; acc[r][1] = 0.0f; }
#pragma unroll 4
            for (int j = 0; j < 64; j++) {
                int k = lane + 32 * j;
                float h0 = __ldg(&x[k]), h1 = __ldg(&x[EMB + k]);
#pragma unroll
                for (int r = 0; r < RPW; r++) {
                    float w = __ldg(&Wih[(size_t)Rg[r] * EMB + k]);
                    acc[r][0] += w * h0; acc[r][1] += w * h1;
                }
            }
        } else {
            // acquire: all CTAs finished step t-1 (t*CTAS arrivals)
            if (tid == 0) {
                unsigned target = (unsigned)t * (unsigned)CTAS;
                while (*((volatile unsigned*)&g_bar) < target) { }
                __threadfence();
            }
            __syncthreads();

            // stage h_{t-1} (fp16, 8KB): 512 threads x uint4
            ((uint4*)sh_h16)[tid] =
                __ldcg(((const uint4*)(g_hseq16 + (size_t)(t - 1) * NB * EMB)) + tid);
            __syncthreads();

            __half2 accH[RPW][2];
            float2  accF[RPW][2];
#pragma unroll
            for (int r = 0; r < RPW; r++) {
                accH[r][0] = __half2half2(__ushort_as_half(0));
                accH[r][1] = __half2half2(__ushort_as_half(0));
                accF[r][0] = make_float2(0.f, 0.f);
                accF[r][1] = make_float2(0.f, 0.f);
            }

            const uint2* sw2 = (const uint2*)sh_w;
#pragma unroll
            for (int m = 0; m < 16; m++) {
                int p = 2 * (lane + 32 * m);     // half2-word index (4 cols)
                uint2 ha = *(const uint2*)&sh_h16[p];
                uint2 hb = *(const uint2*)&sh_h16[1024 + p];
                __half2 hA0 = *(__half2*)&ha.x, hA1 = *(__half2*)&ha.y;
                __half2 hB0 = *(__half2*)&hb.x, hB1 = *(__half2*)&hb.y;
#pragma unroll
                for (int r = 0; r < RPW; r++) {
                    uint2 wv = (m < 4) ? wregA[r][m]
                                       : sw2[rl[r] * 384 + (lane + 32 * m - 128)];
                    __half2 w0 = *(__half2*)&wv.x, w1 = *(__half2*)&wv.y;
                    accH[r][0] = __hfma2(w0, hA0, accH[r][0]);
                    accH[r][0] = __hfma2(w1, hA1, accH[r][0]);
                    accH[r][1] = __hfma2(w0, hB0, accH[r][1]);
                    accH[r][1] = __hfma2(w1, hB1, accH[r][1]);
                }
                // flush fp16 partials to f32 every 4 m-iters (16 terms)
                if ((m & 3) == 3) {
#pragma unroll
                    for (int r = 0; r < RPW; r++)
#pragma unroll
                        for (int b = 0; b < 2; b++) {
                            float2 f = __half22float2(accH[r][b]);
                            accF[r][b].x += f.x; accF[r][b].y += f.y;
                            accH[r][b] = __half2half2(__ushort_as_half(0));
                        }
                }
            }
#pragma unroll
            for (int r = 0; r < RPW; r++) {
                acc[r][0] = accF[r][0].x + accF[r][0].y;
                acc[r][1] = accF[r][1].x + accF[r][1].y;
            }
        }

        // butterfly reduce: all lanes end with complete sums
#pragma unroll
        for (int r = 0; r < RPW; r++)
#pragma unroll
            for (int b = 0; b < 2; b++) {
                float v = acc[r][b];
                v += __shfl_xor_sync(0xffffffffu, v, 16);
                v += __shfl_xor_sync(0xffffffffu, v, 8);
                v += __shfl_xor_sync(0xffffffffu, v, 4);
                v += __shfl_xor_sync(0xffffffffu, v, 2);
                v += __shfl_xor_sync(0xffffffffu, v, 1);
                acc[r][b] = v;
            }

        // lanes 0..7: apply this warp's (single-gate) activation, publish
        if (lane < 8) {
            int r = lane >> 1, b = lane & 1;
            float v = acc[r][b] + bias[r];
            v = (gate == 2) ? tanh_fast(v) : sigmoid_fast(v);
            sh_g[rl[r] * 2 + b] = v;
        }
        __syncthreads();

        // warp 0 tail: combine gates, update c, store h, release + arrive.
        // Warps 1..15 fall through to the next step's poll-sync and wait there.
        if (tid < 32) {
            float ai = sh_g[(0  + my_el) * 2 + my_b];
            float af = sh_g[(16 + my_el) * 2 + my_b];
            float ag = sh_g[(32 + my_el) * 2 + my_b];
            float ao = sh_g[(48 + my_el) * 2 + my_b];
            float cn = af * c_reg + ai * ag;
            c_reg = cn;
            float h = ao * tanh_fast(cn);
            g_hseq16[((size_t)t * NB + my_b) * EMB + e0 + my_el] = __float2half(h);
            if (t != NSTEP - 1) {
                __threadfence();             // writers' release fence (warp 0 only)
                __syncwarp();
                if (lane == 0) atomicAdd(&g_bar, 1u);
            }
        }
        // no trailing block sync: next step's poll-sync provides the ordering
    }
}

// ---------------------------------------------------------------------------
// output projection via wmma fp16 tensor cores:
// out[b][t][n] = hseq[t][b][:] . W_out[n][:] + b_out[n]
// A = g_hseq16 [M=4096][K=2048] row-major (m = t*2+b)
// B = g_Wout16 [N=2048][K=2048] -> matrix_b col_major with ld = EMB
// CTA tile 128x128, 8 warps (2 m x 4 n), warp tile 64x32 = 4x2 frags.
// ---------------------------------------------------------------------------
#define GLDA 40   // smem leading dim (halves), 80B row stride (16B-aligned)

__global__ void __launch_bounds__(256)
out_gemm_wmma(const float* __restrict__ bout, float* __restrict__ out) {
    __shared__ __half As[128 * GLDA];
    __shared__ __half Bs[128 * GLDA];
    __shared__ float  Cst[8 * 16 * 20];

    const int tid = threadIdx.x;
    const int lane = tid & 31;
    const int wid  = tid >> 5;
    const int warp_m = wid & 1;       // 2 x 64 rows
    const int warp_n = wid >> 1;      // 4 x 32 cols
    const int m0 = blockIdx.y * 128;
    const int n0 = blockIdx.x * 128;

    wmma::fragment<wmma::accumulator, 16, 16, 16, float> fc[4][2];
#pragma unroll
    for (int fi = 0; fi < 4; fi++)
#pragma unroll
        for (int fj = 0; fj < 2; fj++)
            wmma::fill_fragment(fc[fi][fj], 0.0f);

    for (int k0 = 0; k0 < EMB; k0 += 32) {
        // cooperative load of A(128x32) and B(128x32) tiles, uint4 = 8 halves
#pragma unroll
        for (int u = 0; u < 2; u++) {
            int i = tid + u * 256;            // [0,512)
            int row = i >> 2, cg = (i & 3) * 8;
            *(uint4*)&As[row * GLDA + cg] =
                *(const uint4*)&g_hseq16[(size_t)(m0 + row) * EMB + k0 + cg];
            *(uint4*)&Bs[row * GLDA + cg] =
                *(const uint4*)&g_Wout16[(size_t)(n0 + row) * EMB + k0 + cg];
        }
        __syncthreads();

#pragma unroll
        for (int ks = 0; ks < 2; ks++) {
            wmma::fragment<wmma::matrix_a, 16, 16, 16, __half, wmma::row_major> fa[4];
            wmma::fragment<wmma::matrix_b, 16, 16, 16, __half, wmma::col_major> fb[2];
#pragma unroll
            for (int fi = 0; fi < 4; fi++)
                wmma::load_matrix_sync(fa[fi],
                    &As[(warp_m * 64 + fi * 16) * GLDA + ks * 16], GLDA);
#pragma unroll
            for (int fj = 0; fj < 2; fj++)
                wmma::load_matrix_sync(fb[fj],
                    &Bs[(warp_n * 32 + fj * 16) * GLDA + ks * 16], GLDA);
#pragma unroll
            for (int fi = 0; fi < 4; fi++)
#pragma unroll
                for (int fj = 0; fj < 2; fj++)
                    wmma::mma_sync(fc[fi][fj], fa[fi], fb[fj], fc[fi][fj]);
        }
        __syncthreads();
    }

    // epilogue: frag -> smem staging -> scattered rows of out (+bias)
    float* bufw = &Cst[wid * 320];
    const int r = lane & 15, h8 = lane >> 4;
#pragma unroll
    for (int fi = 0; fi < 4; fi++) {
#pragma unroll
        for (int fj = 0; fj < 2; fj++) {
            wmma::store_matrix_sync(bufw, fc[fi][fj], 20, wmma::mem_row_major);
            __syncwarp();
            int m = m0 + warp_m * 64 + fi * 16 + r;
            int nb = n0 + warp_n * 32 + fj * 16 + h8 * 8;
            float* orow = &out[((size_t)(m & 1) * NSTEP + (m >> 1)) * EMB];
#pragma unroll
            for (int u = 0; u < 8; u++)
                orow[nb + u] = bufw[r * 20 + h8 * 8 + u] + bout[nb + u];
            __syncwarp();
        }
    }
}

// ---------------------------------------------------------------------------
extern "C" void kernel_launch(void* const* d_in, const int* in_sizes, int n_in,
                              void* d_out, int out_size) {
    const float* x    = (const float*)d_in[0];
    const float* Wih  = (const float*)d_in[1];
    const float* Whh  = (const float*)d_in[2];
    const float* bih  = (const float*)d_in[3];
    const float* bhh  = (const float*)d_in[4];
    const float* Wout = (const float*)d_in[5];
    const float* bout = (const float*)d_in[6];
    float* out = (float*)d_out;

    cudaFuncSetAttribute(lstm_kernel, cudaFuncAttributeMaxDynamicSharedMemorySize, SMEM_BYTES);

    prep_kernel<<<4096, 256>>>(Wih, Whh, bih, bhh, Wout);
    lstm_kernel<<<CTAS, NTHR, SMEM_BYTES>>>(x, Wih);
    dim3 ggrid(EMB / 128, (NSTEP * NB) / 128);
    out_gemm_wmma<<<ggrid, 256>>>(bout, out);
}